// round 1
// baseline (speedup 1.0000x reference)
#include <cuda_runtime.h>
#include <math.h>

#define GAMMA 0.99f
#define LAM   0.95f
#define GL    (GAMMA * LAM)
#define EPSN  1e-8

#define CHUNKS 64
#define MAXN   8192
#define TPB    256
#define MAXPART 8192

// Static device scratch (no allocations allowed).
__device__ float  g_C[CHUNKS * MAXN];      // 2 MB: per-chunk product of coefs
__device__ float  g_D[CHUNKS * MAXN];      // 2 MB: per-chunk affine offset
__device__ float  g_carry[CHUNKS * MAXN];  // 2 MB: carry entering each chunk (from the right)
__device__ double g_part[2 * MAXPART];     // per-block (sum, sumsq) partials
__device__ float  g_mean;
__device__ float  g_inv;                   // 1 / (std + eps)

// ---------------------------------------------------------------------------
// Phase 1: per (chunk, 4-column group), compose the reverse recurrence into
// a_out = D + C * a_in.  C starts at 1, D at 0; step: D = delta + coef*D,
// C = coef*C  (processing t from high to low inside the chunk).
// ---------------------------------------------------------------------------
__global__ __launch_bounds__(TPB)
void gae_phase1(const float* __restrict__ rw, const float* __restrict__ val,
                const int* __restrict__ dn, int T, int N, int L) {
    int groups = N >> 2;
    int tid = blockIdx.x * blockDim.x + threadIdx.x;
    if (tid >= CHUNKS * groups) return;
    int c   = tid / groups;
    int g   = tid - c * groups;
    int col = g << 2;
    int t0  = c * L;
    int t1  = t0 + L - 1;

    float C0 = 1.f, C1 = 1.f, C2 = 1.f, C3 = 1.f;
    float D0 = 0.f, D1 = 0.f, D2 = 0.f, D3 = 0.f;

    float4 vn = *reinterpret_cast<const float4*>(val + (size_t)(t1 + 1) * N + col);
    for (int t = t1; t >= t0; --t) {
        float4 r  = *reinterpret_cast<const float4*>(rw + (size_t)t * N + col);
        int4   d  = *reinterpret_cast<const int4*>(dn + (size_t)t * N + col);
        float4 vc = *reinterpret_cast<const float4*>(val + (size_t)t * N + col);

        float nt, del, cf;
        nt = d.x ? 0.f : 1.f; del = fmaf(GAMMA * nt, vn.x, r.x) - vc.x; cf = GL * nt;
        D0 = fmaf(cf, D0, del); C0 *= cf;
        nt = d.y ? 0.f : 1.f; del = fmaf(GAMMA * nt, vn.y, r.y) - vc.y; cf = GL * nt;
        D1 = fmaf(cf, D1, del); C1 *= cf;
        nt = d.z ? 0.f : 1.f; del = fmaf(GAMMA * nt, vn.z, r.z) - vc.z; cf = GL * nt;
        D2 = fmaf(cf, D2, del); C2 *= cf;
        nt = d.w ? 0.f : 1.f; del = fmaf(GAMMA * nt, vn.w, r.w) - vc.w; cf = GL * nt;
        D3 = fmaf(cf, D3, del); C3 *= cf;

        vn = vc;
    }
    size_t o = (size_t)c * N + col;
    *reinterpret_cast<float4*>(g_C + o) = make_float4(C0, C1, C2, C3);
    *reinterpret_cast<float4*>(g_D + o) = make_float4(D0, D1, D2, D3);
}

// ---------------------------------------------------------------------------
// Phase 2: per 4-column group, reverse-scan over the CHUNKS chunk summaries to
// get the carry (advantage value at each chunk's right boundary).
// ---------------------------------------------------------------------------
__global__ __launch_bounds__(TPB)
void gae_phase2(int N) {
    int groups = N >> 2;
    int g = blockIdx.x * blockDim.x + threadIdx.x;
    if (g >= groups) return;
    int col = g << 2;

    float a0 = 0.f, a1 = 0.f, a2 = 0.f, a3 = 0.f;
    for (int c = CHUNKS - 1; c >= 0; --c) {
        size_t o = (size_t)c * N + col;
        *reinterpret_cast<float4*>(g_carry + o) = make_float4(a0, a1, a2, a3);
        float4 C = *reinterpret_cast<const float4*>(g_C + o);
        float4 D = *reinterpret_cast<const float4*>(g_D + o);
        a0 = fmaf(C.x, a0, D.x);
        a1 = fmaf(C.y, a1, D.y);
        a2 = fmaf(C.z, a2, D.z);
        a3 = fmaf(C.w, a3, D.w);
    }
}

// ---------------------------------------------------------------------------
// Phase 3: re-run the recurrence inside each chunk with the correct carry.
// Write raw advantages and returns; block-reduce (sum, sumsq) into partials.
// ---------------------------------------------------------------------------
__global__ __launch_bounds__(TPB)
void gae_phase3(const float* __restrict__ rw, const float* __restrict__ val,
                const int* __restrict__ dn, float* __restrict__ adv,
                float* __restrict__ ret, int T, int N, int L) {
    int groups = N >> 2;
    int tid = blockIdx.x * blockDim.x + threadIdx.x;

    double s = 0.0, s2 = 0.0;

    if (tid < CHUNKS * groups) {
        int c   = tid / groups;
        int g   = tid - c * groups;
        int col = g << 2;
        int t0  = c * L;
        int t1  = t0 + L - 1;

        size_t co = (size_t)c * N + col;
        float4 a  = *reinterpret_cast<const float4*>(g_carry + co);
        float4 vn = *reinterpret_cast<const float4*>(val + (size_t)(t1 + 1) * N + col);

        for (int t = t1; t >= t0; --t) {
            float4 r  = *reinterpret_cast<const float4*>(rw + (size_t)t * N + col);
            int4   d  = *reinterpret_cast<const int4*>(dn + (size_t)t * N + col);
            float4 vc = *reinterpret_cast<const float4*>(val + (size_t)t * N + col);

            float nt, del;
            nt = d.x ? 0.f : 1.f; del = fmaf(GAMMA * nt, vn.x, r.x) - vc.x;
            a.x = fmaf(GL * nt, a.x, del);
            nt = d.y ? 0.f : 1.f; del = fmaf(GAMMA * nt, vn.y, r.y) - vc.y;
            a.y = fmaf(GL * nt, a.y, del);
            nt = d.z ? 0.f : 1.f; del = fmaf(GAMMA * nt, vn.z, r.z) - vc.z;
            a.z = fmaf(GL * nt, a.z, del);
            nt = d.w ? 0.f : 1.f; del = fmaf(GAMMA * nt, vn.w, r.w) - vc.w;
            a.w = fmaf(GL * nt, a.w, del);

            size_t o = (size_t)t * N + col;
            *reinterpret_cast<float4*>(adv + o) = a;
            *reinterpret_cast<float4*>(ret + o) =
                make_float4(a.x + vc.x, a.y + vc.y, a.z + vc.z, a.w + vc.w);

            s  += (double)a.x + (double)a.y + (double)a.z + (double)a.w;
            s2 += (double)a.x * a.x + (double)a.y * a.y +
                  (double)a.z * a.z + (double)a.w * a.w;

            vn = vc;
        }
    }

    // Block reduction (deterministic; each block owns one partial slot).
    __shared__ double ss[TPB];
    __shared__ double ss2[TPB];
    ss[threadIdx.x]  = s;
    ss2[threadIdx.x] = s2;
    __syncthreads();
    for (int st = TPB / 2; st > 0; st >>= 1) {
        if (threadIdx.x < st) {
            ss[threadIdx.x]  += ss[threadIdx.x + st];
            ss2[threadIdx.x] += ss2[threadIdx.x + st];
        }
        __syncthreads();
    }
    if (threadIdx.x == 0) {
        g_part[2 * blockIdx.x]     = ss[0];
        g_part[2 * blockIdx.x + 1] = ss2[0];
    }
}

// ---------------------------------------------------------------------------
// Phase 4: single block reduces partials -> mean, 1/(std + eps) with ddof=1.
// ---------------------------------------------------------------------------
__global__ void gae_phase4(int nblocks, long long M) {
    __shared__ double ss[512];
    __shared__ double ss2[512];
    double s = 0.0, s2 = 0.0;
    for (int i = threadIdx.x; i < nblocks; i += 512) {
        s  += g_part[2 * i];
        s2 += g_part[2 * i + 1];
    }
    ss[threadIdx.x]  = s;
    ss2[threadIdx.x] = s2;
    __syncthreads();
    for (int st = 256; st > 0; st >>= 1) {
        if (threadIdx.x < st) {
            ss[threadIdx.x]  += ss[threadIdx.x + st];
            ss2[threadIdx.x] += ss2[threadIdx.x + st];
        }
        __syncthreads();
    }
    if (threadIdx.x == 0) {
        double mean = ss[0] / (double)M;
        double var  = (ss2[0] - ss[0] * ss[0] / (double)M) / (double)(M - 1);
        if (var < 0.0) var = 0.0;
        g_mean = (float)mean;
        g_inv  = (float)(1.0 / (sqrt(var) + EPSN));
    }
}

// ---------------------------------------------------------------------------
// Phase 5: in-place normalize advantages.
// ---------------------------------------------------------------------------
__global__ __launch_bounds__(TPB)
void gae_phase5(float* __restrict__ adv, size_t M4) {
    size_t i = (size_t)blockIdx.x * blockDim.x + threadIdx.x;
    if (i >= M4) return;
    float m = g_mean, inv = g_inv;
    float4 x = reinterpret_cast<float4*>(adv)[i];
    x.x = (x.x - m) * inv;
    x.y = (x.y - m) * inv;
    x.z = (x.z - m) * inv;
    x.w = (x.w - m) * inv;
    reinterpret_cast<float4*>(adv)[i] = x;
}

extern "C" void kernel_launch(void* const* d_in, const int* in_sizes, int n_in,
                              void* d_out, int out_size) {
    const float* rw  = (const float*)d_in[0];   // rewards [T, N]
    const float* val = (const float*)d_in[1];   // values  [T+1, N]
    const int*   dn  = (const int*)d_in[2];     // dones   [T, N]
    float* out = (float*)d_out;                 // [adv_norm TN | returns TN]

    int TN = in_sizes[0];
    int N  = in_sizes[1] - in_sizes[0];         // values - rewards = N
    int T  = TN / N;
    int L  = T / CHUNKS;

    int groups  = N >> 2;
    int nth     = CHUNKS * groups;
    int blocks1 = (nth + TPB - 1) / TPB;

    float* adv = out;
    float* ret = out + (size_t)TN;

    gae_phase1<<<blocks1, TPB>>>(rw, val, dn, T, N, L);
    gae_phase2<<<(groups + TPB - 1) / TPB, TPB>>>(N);
    gae_phase3<<<blocks1, TPB>>>(rw, val, dn, adv, ret, T, N, L);
    gae_phase4<<<1, 512>>>(blocks1, (long long)TN);
    size_t M4 = (size_t)TN >> 2;
    gae_phase5<<<(int)((M4 + TPB - 1) / TPB), TPB>>>(adv, M4);
}

// round 2
// speedup vs baseline: 1.8950x; 1.8950x over previous
#include <cuda_runtime.h>
#include <math.h>

#define GAMMA 0.99f
#define LAM   0.95f
#define GL    (GAMMA * LAM)
#define EPSN  1e-8

#define CHUNKS 64
#define MAXN   8192
#define TPB    256
#define P2BLK  ((MAXN + TPB - 1) / TPB)   // 32 partial slots

// Static device scratch (no allocations allowed).
__device__ float  g_C  [CHUNKS * MAXN];
__device__ float  g_D  [CHUNKS * MAXN];
__device__ float  g_S1 [CHUNKS * MAXN];
__device__ float  g_SC [CHUNKS * MAXN];
__device__ float  g_S2 [CHUNKS * MAXN];
__device__ float  g_SDC[CHUNKS * MAXN];
__device__ float  g_SC2[CHUNKS * MAXN];
__device__ float  g_carry[CHUNKS * MAXN];
__device__ double g_part[2 * P2BLK];
__device__ float  g_mean;
__device__ float  g_inv;   // 1 / (std + eps)

// ---------------------------------------------------------------------------
// Phase 1: per (chunk, 4-column group), compose the reverse recurrence into
// a_out = D + C * a_in and accumulate sufficient statistics so the global
// mean/std can be computed from chunk summaries alone (no second reduction
// pass over the 16.7M advantages).
// ---------------------------------------------------------------------------
__global__ __launch_bounds__(TPB)
void gae_phase1(const float* __restrict__ rw, const float* __restrict__ val,
                const int* __restrict__ dn, int N, int L) {
    int groups = N >> 2;
    int tid = blockIdx.x * blockDim.x + threadIdx.x;
    if (tid >= CHUNKS * groups) return;
    int c   = tid / groups;
    int g   = tid - c * groups;
    int col = g << 2;
    int t0  = c * L;
    int t1  = t0 + L - 1;

    float C[4]  = {1.f, 1.f, 1.f, 1.f};
    float D[4]  = {0.f, 0.f, 0.f, 0.f};
    float S1[4] = {0.f, 0.f, 0.f, 0.f};
    float SC[4] = {0.f, 0.f, 0.f, 0.f};
    float S2[4] = {0.f, 0.f, 0.f, 0.f};
    float SDC[4]= {0.f, 0.f, 0.f, 0.f};
    float SC2[4]= {0.f, 0.f, 0.f, 0.f};

    float4 vn = *reinterpret_cast<const float4*>(val + (size_t)(t1 + 1) * N + col);
    #pragma unroll 4
    for (int t = t1; t >= t0; --t) {
        float4 r  = *reinterpret_cast<const float4*>(rw + (size_t)t * N + col);
        int4   dd = *reinterpret_cast<const int4*>(dn + (size_t)t * N + col);
        float4 vc = *reinterpret_cast<const float4*>(val + (size_t)t * N + col);

        float rr[4] = {r.x, r.y, r.z, r.w};
        float vv[4] = {vc.x, vc.y, vc.z, vc.w};
        float vnn[4]= {vn.x, vn.y, vn.z, vn.w};
        int   di[4] = {dd.x, dd.y, dd.z, dd.w};

        #pragma unroll
        for (int j = 0; j < 4; ++j) {
            float nt  = di[j] ? 0.f : 1.f;
            float del = fmaf(GAMMA * nt, vnn[j], rr[j]) - vv[j];
            float cf  = GL * nt;
            D[j] = fmaf(cf, D[j], del);
            C[j] *= cf;
            S1[j] += D[j];
            SC[j] += C[j];
            S2[j]  = fmaf(D[j], D[j], S2[j]);
            SDC[j] = fmaf(D[j], C[j], SDC[j]);
            SC2[j] = fmaf(C[j], C[j], SC2[j]);
        }
        vn = vc;
    }
    size_t o = (size_t)c * N + col;
    *reinterpret_cast<float4*>(g_C   + o) = make_float4(C[0],  C[1],  C[2],  C[3]);
    *reinterpret_cast<float4*>(g_D   + o) = make_float4(D[0],  D[1],  D[2],  D[3]);
    *reinterpret_cast<float4*>(g_S1  + o) = make_float4(S1[0], S1[1], S1[2], S1[3]);
    *reinterpret_cast<float4*>(g_SC  + o) = make_float4(SC[0], SC[1], SC[2], SC[3]);
    *reinterpret_cast<float4*>(g_S2  + o) = make_float4(S2[0], S2[1], S2[2], S2[3]);
    *reinterpret_cast<float4*>(g_SDC + o) = make_float4(SDC[0],SDC[1],SDC[2],SDC[3]);
    *reinterpret_cast<float4*>(g_SC2 + o) = make_float4(SC2[0],SC2[1],SC2[2],SC2[3]);
}

// ---------------------------------------------------------------------------
// Phase 2: one thread per column. Reverse-scan the CHUNKS chunk summaries to
// produce carries, while accumulating the column's total sum and sumsq of
// advantages via the closed forms:
//   sum_chunk   = S1 + SC*a
//   sumsq_chunk = S2 + 2*SDC*a + SC2*a*a
// Column totals accumulate in float (64 terms); block reduction in double.
// ---------------------------------------------------------------------------
__global__ __launch_bounds__(TPB)
void gae_phase2(int N) {
    int col = blockIdx.x * blockDim.x + threadIdx.x;
    float ts = 0.f, ts2 = 0.f;
    if (col < N) {
        float a = 0.f;
        #pragma unroll 4
        for (int c = CHUNKS - 1; c >= 0; --c) {
            size_t o = (size_t)c * N + col;
            g_carry[o] = a;
            float C   = g_C[o],   D   = g_D[o];
            float S1  = g_S1[o],  SC  = g_SC[o];
            float S2  = g_S2[o],  SDC = g_SDC[o], SC2 = g_SC2[o];
            ts  += fmaf(SC, a, S1);
            ts2 += fmaf(fmaf(SC2, a, 2.f * SDC), a, S2);
            a = fmaf(C, a, D);
        }
    }
    __shared__ double ss[TPB];
    __shared__ double ss2[TPB];
    ss[threadIdx.x]  = (double)ts;
    ss2[threadIdx.x] = (double)ts2;
    __syncthreads();
    for (int st = TPB / 2; st > 0; st >>= 1) {
        if (threadIdx.x < st) {
            ss[threadIdx.x]  += ss[threadIdx.x + st];
            ss2[threadIdx.x] += ss2[threadIdx.x + st];
        }
        __syncthreads();
    }
    if (threadIdx.x == 0) {
        g_part[2 * blockIdx.x]     = ss[0];
        g_part[2 * blockIdx.x + 1] = ss2[0];
    }
}

// ---------------------------------------------------------------------------
// Phase 3 (finalize stats): single tiny block -> mean, 1/(std+eps), ddof=1.
// ---------------------------------------------------------------------------
__global__ void gae_finalize(int nblocks, long long M) {
    __shared__ double ss[64];
    __shared__ double ss2[64];
    double s = 0.0, s2 = 0.0;
    for (int i = threadIdx.x; i < nblocks; i += 64) {
        s  += g_part[2 * i];
        s2 += g_part[2 * i + 1];
    }
    ss[threadIdx.x]  = s;
    ss2[threadIdx.x] = s2;
    __syncthreads();
    for (int st = 32; st > 0; st >>= 1) {
        if (threadIdx.x < st) {
            ss[threadIdx.x]  += ss[threadIdx.x + st];
            ss2[threadIdx.x] += ss2[threadIdx.x + st];
        }
        __syncthreads();
    }
    if (threadIdx.x == 0) {
        double mean = ss[0] / (double)M;
        double var  = (ss2[0] - ss[0] * ss[0] / (double)M) / (double)(M - 1);
        if (var < 0.0) var = 0.0;
        g_mean = (float)mean;
        g_inv  = (float)(1.0 / (sqrt(var) + EPSN));
    }
}

// ---------------------------------------------------------------------------
// Phase 4: replay recurrence with correct carry; write NORMALIZED advantages
// and returns directly. No FP64, no reductions.
// ---------------------------------------------------------------------------
__global__ __launch_bounds__(TPB)
void gae_write(const float* __restrict__ rw, const float* __restrict__ val,
               const int* __restrict__ dn, float* __restrict__ adv,
               float* __restrict__ ret, int N, int L) {
    int groups = N >> 2;
    int tid = blockIdx.x * blockDim.x + threadIdx.x;
    if (tid >= CHUNKS * groups) return;
    int c   = tid / groups;
    int g   = tid - c * groups;
    int col = g << 2;
    int t0  = c * L;
    int t1  = t0 + L - 1;

    float m   = g_mean;
    float inv = g_inv;

    size_t co = (size_t)c * N + col;
    float4 a  = *reinterpret_cast<const float4*>(g_carry + co);
    float4 vn = *reinterpret_cast<const float4*>(val + (size_t)(t1 + 1) * N + col);

    #pragma unroll 4
    for (int t = t1; t >= t0; --t) {
        float4 r  = *reinterpret_cast<const float4*>(rw + (size_t)t * N + col);
        int4   dd = *reinterpret_cast<const int4*>(dn + (size_t)t * N + col);
        float4 vc = *reinterpret_cast<const float4*>(val + (size_t)t * N + col);

        float nt, del;
        nt = dd.x ? 0.f : 1.f; del = fmaf(GAMMA * nt, vn.x, r.x) - vc.x;
        a.x = fmaf(GL * nt, a.x, del);
        nt = dd.y ? 0.f : 1.f; del = fmaf(GAMMA * nt, vn.y, r.y) - vc.y;
        a.y = fmaf(GL * nt, a.y, del);
        nt = dd.z ? 0.f : 1.f; del = fmaf(GAMMA * nt, vn.z, r.z) - vc.z;
        a.z = fmaf(GL * nt, a.z, del);
        nt = dd.w ? 0.f : 1.f; del = fmaf(GAMMA * nt, vn.w, r.w) - vc.w;
        a.w = fmaf(GL * nt, a.w, del);

        size_t o = (size_t)t * N + col;
        *reinterpret_cast<float4*>(adv + o) =
            make_float4((a.x - m) * inv, (a.y - m) * inv,
                        (a.z - m) * inv, (a.w - m) * inv);
        *reinterpret_cast<float4*>(ret + o) =
            make_float4(a.x + vc.x, a.y + vc.y, a.z + vc.z, a.w + vc.w);

        vn = vc;
    }
}

extern "C" void kernel_launch(void* const* d_in, const int* in_sizes, int n_in,
                              void* d_out, int out_size) {
    const float* rw  = (const float*)d_in[0];   // rewards [T, N]
    const float* val = (const float*)d_in[1];   // values  [T+1, N]
    const int*   dn  = (const int*)d_in[2];     // dones   [T, N]
    float* out = (float*)d_out;                 // [adv_norm TN | returns TN]

    int TN = in_sizes[0];
    int N  = in_sizes[1] - in_sizes[0];
    int T  = TN / N;
    int L  = T / CHUNKS;

    int groups  = N >> 2;
    int nth     = CHUNKS * groups;
    int blocks1 = (nth + TPB - 1) / TPB;
    int blocks2 = (N + TPB - 1) / TPB;

    float* adv = out;
    float* ret = out + (size_t)TN;

    gae_phase1<<<blocks1, TPB>>>(rw, val, dn, N, L);
    gae_phase2<<<blocks2, TPB>>>(N);
    gae_finalize<<<1, 64>>>(blocks2, (long long)TN);
    gae_write<<<blocks1, TPB>>>(rw, val, dn, adv, ret, N, L);
}